// round 7
// baseline (speedup 1.0000x reference)
#include <cuda_runtime.h>
#include <cuda_bf16.h>
#include <cstdint>

// ---------------- problem constants ----------------
#define N_NODES 100000
#define N_EDGES 1600000
#define IN_DIM 64
#define HID 128
#define OUT_DIM 9

// ---------------- static scratch (no allocation allowed) ----------------
__device__ int g_cnt[N_NODES];
__device__ int g_start[N_NODES + 1];
__device__ int g_cursor[N_NODES];
__device__ int g_perm[N_EDGES];
__device__ int g_bsum[512];

__device__ __nv_bfloat16 g_xhi[(size_t)N_NODES * IN_DIM];
__device__ __nv_bfloat16 g_xlo[(size_t)N_NODES * IN_DIM];
__device__ __nv_bfloat16 g_mhi[(size_t)N_NODES * HID];         // mean hi
__device__ __nv_bfloat16 g_mlo[(size_t)N_NODES * HID];         // mean lo
__device__ float g_h[(size_t)N_NODES * HID];                   // h1 then h2 (fp32, gather source)
__device__ __nv_bfloat16 g_hhi[(size_t)N_NODES * HID];
__device__ __nv_bfloat16 g_hlo[(size_t)N_NODES * HID];
__device__ float g_h3[(size_t)N_NODES * 2 * HID];
// static weight buffers (bf16, transposed [N,K]); order: l1l_hi,l1l_lo,l1r_hi,l1r_lo, l2..., l3...
__device__ __nv_bfloat16 g_w[12][256 * 128];

// ---------------- PTX helpers (all plain sm_80+ — no 'a' features) ----------------
__device__ __forceinline__ uint32_t smem_u32(const void* p) {
    uint32_t a;
    asm("{ .reg .u64 t; cvta.to.shared.u64 t, %1; cvt.u32.u64 %0, t; }" : "=r"(a) : "l"(p));
    return a;
}

__device__ __forceinline__ void cp_async16(uint32_t dst, const void* src, int src_bytes) {
    asm volatile("cp.async.cg.shared.global [%0], [%1], 16, %2;"
                 :: "r"(dst), "l"(src), "r"(src_bytes));
}
#define CP_COMMIT() asm volatile("cp.async.commit_group;" ::: "memory")
#define CP_WAIT_1() asm volatile("cp.async.wait_group 1;" ::: "memory")

__device__ __forceinline__ void ldm_x4(uint32_t& r0, uint32_t& r1, uint32_t& r2, uint32_t& r3,
                                       uint32_t addr) {
    asm volatile("ldmatrix.sync.aligned.m8n8.x4.shared.b16 {%0,%1,%2,%3}, [%4];"
                 : "=r"(r0), "=r"(r1), "=r"(r2), "=r"(r3) : "r"(addr));
}

__device__ __forceinline__ void mma_16816(float* c, const uint32_t* a, const uint32_t* b) {
    asm volatile(
        "mma.sync.aligned.m16n8k16.row.col.f32.bf16.bf16.f32 "
        "{%0,%1,%2,%3}, {%4,%5,%6,%7}, {%8,%9}, {%0,%1,%2,%3};"
        : "+f"(c[0]), "+f"(c[1]), "+f"(c[2]), "+f"(c[3])
        : "r"(a[0]), "r"(a[1]), "r"(a[2]), "r"(a[3]), "r"(b[0]), "r"(b[1]));
}

// ---------------- CSR build kernels ----------------
__global__ void zero_int(int* __restrict__ p, int n) {
    int i = blockIdx.x * blockDim.x + threadIdx.x;
    if (i < n) p[i] = 0;
}

__global__ void hist_kernel(const int* __restrict__ dst, int* __restrict__ cnt, int E) {
    int e = blockIdx.x * blockDim.x + threadIdx.x;
    if (e < E) atomicAdd(&cnt[dst[e]], 1);
}

#define SCAN_B 256
__global__ void block_sum(const int* __restrict__ cnt, int* __restrict__ bsum, int n) {
    __shared__ int sh[SCAN_B];
    int i = blockIdx.x * SCAN_B + threadIdx.x;
    sh[threadIdx.x] = (i < n) ? cnt[i] : 0;
    __syncthreads();
    #pragma unroll
    for (int off = SCAN_B / 2; off > 0; off >>= 1) {
        if (threadIdx.x < off) sh[threadIdx.x] += sh[threadIdx.x + off];
        __syncthreads();
    }
    if (threadIdx.x == 0) bsum[blockIdx.x] = sh[0];
}

// single block of 512 threads: exclusive scan of nb block sums; also writes start[N]=E total
__global__ void scan_bsums(int* __restrict__ bsum, int nb, int* __restrict__ startN) {
    __shared__ int sh[512];
    int t = threadIdx.x;
    int orig = (t < nb) ? bsum[t] : 0;
    sh[t] = orig;
    __syncthreads();
    #pragma unroll
    for (int off = 1; off < 512; off <<= 1) {
        int v = (t >= off) ? sh[t - off] : 0;
        __syncthreads();
        sh[t] += v;
        __syncthreads();
    }
    if (t < nb) bsum[t] = sh[t] - orig;   // exclusive prefix
    if (t == 0) startN[0] = sh[511];      // total = E
}

__global__ void block_scan(const int* __restrict__ cnt, const int* __restrict__ boff,
                           int* __restrict__ start, int* __restrict__ cursor, int n) {
    __shared__ int sh[SCAN_B];
    int i = blockIdx.x * SCAN_B + threadIdx.x;
    int t = threadIdx.x;
    int v = (i < n) ? cnt[i] : 0;
    sh[t] = v;
    __syncthreads();
    #pragma unroll
    for (int off = 1; off < SCAN_B; off <<= 1) {
        int u = (t >= off) ? sh[t - off] : 0;
        __syncthreads();
        sh[t] += u;
        __syncthreads();
    }
    if (i < n) {
        int ex = boff[blockIdx.x] + sh[t] - v;
        start[i] = ex;
        cursor[i] = ex;
    }
}

__global__ void fill_perm(const int* __restrict__ src, const int* __restrict__ dst,
                          int* __restrict__ cursor, int* __restrict__ perm, int E) {
    int e = blockIdx.x * blockDim.x + threadIdx.x;
    if (e < E) {
        int pos = atomicAdd(&cursor[dst[e]], 1);
        perm[pos] = src[e];
    }
}

// ---------------- CSR gather-aggregate + mean + bf16 hi/lo split ----------------
// DV = feature dim / 4 (float4 units per row). DV=32: warp per node. DV=16: 2 nodes per warp.
template <int DV>
__global__ __launch_bounds__(256)
void agg_csr(const float4* __restrict__ x, const int* __restrict__ start,
             const int* __restrict__ perm,
             __nv_bfloat16* __restrict__ hi, __nv_bfloat16* __restrict__ lo, int n) {
    int gw = (blockIdx.x * blockDim.x + threadIdx.x) >> 5;
    int lane = threadIdx.x & 31;
    int node, c;
    if (DV == 32) { node = gw; c = lane; }
    else          { node = gw * 2 + (lane >> 4); c = lane & 15; }
    if (node >= n) return;
    int s = __ldg(&start[node]);
    int e = __ldg(&start[node + 1]);
    float4 acc = make_float4(0.f, 0.f, 0.f, 0.f);
    int j = s;
    for (; j + 4 <= e; j += 4) {
        int p0 = __ldg(&perm[j]);
        int p1 = __ldg(&perm[j + 1]);
        int p2 = __ldg(&perm[j + 2]);
        int p3 = __ldg(&perm[j + 3]);
        float4 v0 = __ldg(&x[(size_t)p0 * DV + c]);
        float4 v1 = __ldg(&x[(size_t)p1 * DV + c]);
        float4 v2 = __ldg(&x[(size_t)p2 * DV + c]);
        float4 v3 = __ldg(&x[(size_t)p3 * DV + c]);
        acc.x += v0.x + v1.x + v2.x + v3.x;
        acc.y += v0.y + v1.y + v2.y + v3.y;
        acc.z += v0.z + v1.z + v2.z + v3.z;
        acc.w += v0.w + v1.w + v2.w + v3.w;
    }
    for (; j < e; j++) {
        int p = __ldg(&perm[j]);
        float4 v = __ldg(&x[(size_t)p * DV + c]);
        acc.x += v.x; acc.y += v.y; acc.z += v.z; acc.w += v.w;
    }
    float r = 1.0f / fmaxf((float)(e - s), 1.0f);
    float m[4] = {acc.x * r, acc.y * r, acc.z * r, acc.w * r};
    __nv_bfloat16 hb[4], lb[4];
    #pragma unroll
    for (int q = 0; q < 4; q++) {
        hb[q] = __float2bfloat16(m[q]);
        lb[q] = __float2bfloat16(m[q] - __bfloat162float(hb[q]));
    }
    size_t off = (size_t)node * (DV * 4) + c * 4;
    *(uint2*)(hi + off) = *(uint2*)hb;
    *(uint2*)(lo + off) = *(uint2*)lb;
}

// ---------------- misc split kernels ----------------
__global__ void split_kernel(const float* __restrict__ x,
                             __nv_bfloat16* __restrict__ hi, __nv_bfloat16* __restrict__ lo, int n) {
    int i = blockIdx.x * blockDim.x + threadIdx.x;
    if (i >= n) return;
    float v = x[i];
    __nv_bfloat16 h = __float2bfloat16(v);
    hi[i] = h;
    lo[i] = __float2bfloat16(v - __bfloat162float(h));
}

__global__ void wsplit_kernel(const float* __restrict__ W,
                              __nv_bfloat16* __restrict__ hi, __nv_bfloat16* __restrict__ lo,
                              int K, int N) {
    int idx = blockIdx.x * blockDim.x + threadIdx.x;
    if (idx >= K * N) return;
    int k = idx / N, n = idx % N;
    float v = W[idx];
    __nv_bfloat16 h = __float2bfloat16(v);
    hi[(size_t)n * K + k] = h;
    lo[(size_t)n * K + k] = __float2bfloat16(v - __bfloat162float(h));
}

// ---------------- mma.sync dual-A split-bf16 GEMM (unchanged from R5, passing) ----------------
template <bool SPLIT_OUT>
__global__ __launch_bounds__(256, 2)
void gemm_mma(const __nv_bfloat16* __restrict__ A1hi, const __nv_bfloat16* __restrict__ A1lo,
              const __nv_bfloat16* __restrict__ A2hi, const __nv_bfloat16* __restrict__ A2lo,
              const __nv_bfloat16* __restrict__ B1hi, const __nv_bfloat16* __restrict__ B1lo,
              const __nv_bfloat16* __restrict__ B2hi, const __nv_bfloat16* __restrict__ B2lo,
              const float* __restrict__ bias, float* __restrict__ C,
              __nv_bfloat16* __restrict__ Chi, __nv_bfloat16* __restrict__ Clo,
              int M, int Ntot, int Kseg) {
    extern __shared__ char smem_raw[];
    char* smem = (char*)(((uintptr_t)smem_raw + 127) & ~(uintptr_t)127);
    const uint32_t sbase = smem_u32(smem);

    const int tid = threadIdx.x;
    const int wid = tid >> 5;
    const int lane = tid & 31;
    const int warp_m = wid & 3;
    const int warp_n = wid >> 2;
    const int bm = blockIdx.x * 128;
    const int bn = blockIdx.y * 128;

    const int STG = 32768;
    const int BOFF = 16384;

    const __nv_bfloat16* As[6] = {A1hi, A1hi, A1lo, A2hi, A2hi, A2lo};
    const __nv_bfloat16* Bs[6] = {B1hi, B1lo, B1hi, B2hi, B2lo, B2hi};
    const int cps = Kseg >> 6;
    const int nch = 6 * cps;

    float acc[2][8][4];
    #pragma unroll
    for (int mi = 0; mi < 2; mi++)
        #pragma unroll
        for (int ni = 0; ni < 8; ni++)
            #pragma unroll
            for (int q = 0; q < 4; q++) acc[mi][ni][q] = 0.0f;

    auto load_stage = [&](int stage, int c) {
        const int seg = c / cps;
        const int sub = c - seg * cps;
        const __nv_bfloat16* Ab = As[seg];
        const __nv_bfloat16* Bb = Bs[seg];
        const int kofs = sub << 6;
        #pragma unroll
        for (int p = 0; p < 4; p++) {
            int ci = tid + p * 256;
            int row = ci >> 3;
            int ch = ci & 7;
            uint32_t dstp = sbase + stage * STG + row * 128 + ((ch ^ (row & 7)) << 4);
            int grow = bm + row;
            int ok = (grow < M) ? 16 : 0;
            int gr = (grow < M) ? grow : (M - 1);
            cp_async16(dstp, Ab + (size_t)gr * Kseg + kofs + ch * 8, ok);
        }
        #pragma unroll
        for (int p = 0; p < 4; p++) {
            int ci = tid + p * 256;
            int row = ci >> 3;
            int ch = ci & 7;
            uint32_t dstp = sbase + stage * STG + BOFF + row * 128 + ((ch ^ (row & 7)) << 4);
            cp_async16(dstp, Bb + (size_t)(bn + row) * Kseg + kofs + ch * 8, 16);
        }
    };

    const int arow = warp_m * 32 + (lane & 15);
    const int asel = (lane >> 4);
    const int brow = warp_n * 64 + (lane & 7) + ((lane & 16) >> 1);
    const int bsel = (lane >> 3) & 1;

    load_stage(0, 0);
    CP_COMMIT();

    for (int c = 0; c < nch; c++) {
        const int s = c & 1;
        if (c + 1 < nch) load_stage(s ^ 1, c + 1);
        CP_COMMIT();
        CP_WAIT_1();
        __syncthreads();

        const uint32_t Abase = sbase + s * STG;
        const uint32_t Bbase = sbase + s * STG + BOFF;
        #pragma unroll
        for (int kc = 0; kc < 4; kc++) {
            uint32_t a[2][4];
            #pragma unroll
            for (int mi = 0; mi < 2; mi++) {
                int r = arow + mi * 16;
                uint32_t ad = Abase + r * 128 + (((kc * 2 + asel) ^ (r & 7)) << 4);
                ldm_x4(a[mi][0], a[mi][1], a[mi][2], a[mi][3], ad);
            }
            uint32_t b[8][2];
            #pragma unroll
            for (int nj = 0; nj < 4; nj++) {
                int r = brow + nj * 16;
                uint32_t bd = Bbase + r * 128 + (((kc * 2 + bsel) ^ (r & 7)) << 4);
                uint32_t t0, t1, t2, t3;
                ldm_x4(t0, t1, t2, t3, bd);
                b[nj * 2][0] = t0; b[nj * 2][1] = t1;
                b[nj * 2 + 1][0] = t2; b[nj * 2 + 1][1] = t3;
            }
            #pragma unroll
            for (int mi = 0; mi < 2; mi++)
                #pragma unroll
                for (int ni = 0; ni < 8; ni++)
                    mma_16816(acc[mi][ni], a[mi], b[ni]);
        }
        __syncthreads();
    }

    const int col0 = bn + warp_n * 64 + (lane & 3) * 2;
    #pragma unroll
    for (int mi = 0; mi < 2; mi++) {
        int row0 = bm + warp_m * 32 + mi * 16 + (lane >> 2);
        #pragma unroll
        for (int half = 0; half < 2; half++) {
            int row = row0 + half * 8;
            if (row >= M) continue;
            #pragma unroll
            for (int ni = 0; ni < 8; ni++) {
                int col = col0 + ni * 8;
                float v0 = acc[mi][ni][half * 2 + 0] + __ldg(&bias[col]);
                float v1 = acc[mi][ni][half * 2 + 1] + __ldg(&bias[col + 1]);
                v0 = fmaxf(v0, 0.0f);
                v1 = fmaxf(v1, 0.0f);
                *(float2*)(C + (size_t)row * Ntot + col) = make_float2(v0, v1);
                if (SPLIT_OUT) {
                    __nv_bfloat16 h0 = __float2bfloat16(v0);
                    __nv_bfloat16 h1 = __float2bfloat16(v1);
                    __nv_bfloat16 l0 = __float2bfloat16(v0 - __bfloat162float(h0));
                    __nv_bfloat16 l1 = __float2bfloat16(v1 - __bfloat162float(h1));
                    *(__nv_bfloat162*)(Chi + (size_t)row * Ntot + col) = __nv_bfloat162(h0, h1);
                    *(__nv_bfloat162*)(Clo + (size_t)row * Ntot + col) = __nv_bfloat162(l0, l1);
                }
            }
        }
    }
}

// ---------------- FC head: out[i,0..8] = h3[i,:]@Wfc + bfc (warp per node) ----
__global__ void fc_kernel(const float* __restrict__ h3, const float* __restrict__ W,
                          const float* __restrict__ b, float* __restrict__ out, int M) {
    int gwarp = (blockIdx.x * blockDim.x + threadIdx.x) >> 5;
    int lane = threadIdx.x & 31;
    if (gwarp >= M) return;
    const float* row = h3 + (size_t)gwarp * (2 * HID);
    float acc[OUT_DIM];
    #pragma unroll
    for (int j = 0; j < OUT_DIM; j++) acc[j] = 0.0f;
    for (int k = lane; k < 2 * HID; k += 32) {
        float a = row[k];
        #pragma unroll
        for (int j = 0; j < OUT_DIM; j++)
            acc[j] = fmaf(a, W[k * OUT_DIM + j], acc[j]);
    }
    #pragma unroll
    for (int j = 0; j < OUT_DIM; j++) {
        #pragma unroll
        for (int off = 16; off > 0; off >>= 1)
            acc[j] += __shfl_down_sync(0xffffffffu, acc[j], off);
    }
    if (lane == 0) {
        #pragma unroll
        for (int j = 0; j < OUT_DIM; j++)
            out[(size_t)gwarp * OUT_DIM + j] = acc[j] + b[j];
    }
}

// ---------------- host launch ----------------
static inline int cdiv(int a, int b) { return (a + b - 1) / b; }

extern "C" void kernel_launch(void* const* d_in, const int* in_sizes, int n_in,
                              void* d_out, int out_size) {
    const float* x   = (const float*)d_in[0];
    const int* eidx  = (const int*)d_in[1];
    const float* Wl1 = (const float*)d_in[2];
    const float* bl1 = (const float*)d_in[3];
    const float* Wr1 = (const float*)d_in[4];
    const float* Wl2 = (const float*)d_in[5];
    const float* bl2 = (const float*)d_in[6];
    const float* Wr2 = (const float*)d_in[7];
    const float* Wl3 = (const float*)d_in[8];
    const float* bl3 = (const float*)d_in[9];
    const float* Wr3 = (const float*)d_in[10];
    const float* Wfc = (const float*)d_in[11];
    const float* bfc = (const float*)d_in[12];
    float* out = (float*)d_out;

    const int M = in_sizes[0] / IN_DIM;       // 100000
    const int E = in_sizes[1] / 2;            // 1600000
    const int* src = eidx;
    const int* dst = eidx + E;

    float *h, *h3;
    int *cnt, *start, *cursor, *perm, *bsum;
    __nv_bfloat16 *xhi, *xlo, *mhi, *mlo, *hhi, *hlo, *w;
    cudaGetSymbolAddress((void**)&cnt, g_cnt);
    cudaGetSymbolAddress((void**)&start, g_start);
    cudaGetSymbolAddress((void**)&cursor, g_cursor);
    cudaGetSymbolAddress((void**)&perm, g_perm);
    cudaGetSymbolAddress((void**)&bsum, g_bsum);
    cudaGetSymbolAddress((void**)&h, g_h);
    cudaGetSymbolAddress((void**)&h3, g_h3);
    cudaGetSymbolAddress((void**)&xhi, g_xhi);
    cudaGetSymbolAddress((void**)&xlo, g_xlo);
    cudaGetSymbolAddress((void**)&mhi, g_mhi);
    cudaGetSymbolAddress((void**)&mlo, g_mlo);
    cudaGetSymbolAddress((void**)&hhi, g_hhi);
    cudaGetSymbolAddress((void**)&hlo, g_hlo);
    cudaGetSymbolAddress((void**)&w, g_w);
    const size_t WSTRIDE = 256 * 128;
    __nv_bfloat16* wp[12];
    for (int i = 0; i < 12; i++) wp[i] = w + i * WSTRIDE;

    const int T = 256;
    const int SMEM_GEMM = 2 * 32768 + 128;

    cudaFuncSetAttribute(gemm_mma<true>, cudaFuncAttributeMaxDynamicSharedMemorySize, SMEM_GEMM);
    cudaFuncSetAttribute(gemm_mma<false>, cudaFuncAttributeMaxDynamicSharedMemorySize, SMEM_GEMM);

    // ---- CSR build (once per launch; reused by all 3 layers) ----
    const int NB = cdiv(M, SCAN_B);           // 391
    zero_int<<<cdiv(M, T), T>>>(cnt, M);
    hist_kernel<<<cdiv(E, T), T>>>(dst, cnt, E);
    block_sum<<<NB, SCAN_B>>>(cnt, bsum, M);
    scan_bsums<<<1, 512>>>(bsum, NB, start + M);
    block_scan<<<NB, SCAN_B>>>(cnt, bsum, start, cursor, M);
    fill_perm<<<cdiv(E, T), T>>>(src, dst, cursor, perm, E);

    // ---- one-time splits: x and weights ----
    split_kernel<<<cdiv(M * IN_DIM, T), T>>>(x, xhi, xlo, M * IN_DIM);
    wsplit_kernel<<<cdiv(IN_DIM * HID, T), T>>>(Wl1, wp[0], wp[1], IN_DIM, HID);
    wsplit_kernel<<<cdiv(IN_DIM * HID, T), T>>>(Wr1, wp[2], wp[3], IN_DIM, HID);
    wsplit_kernel<<<cdiv(HID * HID, T), T>>>(Wl2, wp[4], wp[5], HID, HID);
    wsplit_kernel<<<cdiv(HID * HID, T), T>>>(Wr2, wp[6], wp[7], HID, HID);
    wsplit_kernel<<<cdiv(HID * 2 * HID, T), T>>>(Wl3, wp[8], wp[9], HID, 2 * HID);
    wsplit_kernel<<<cdiv(HID * 2 * HID, T), T>>>(Wr3, wp[10], wp[11], HID, 2 * HID);

    const int MT = cdiv(M, 128);   // 782 m-tiles
    const int W128 = cdiv(M * 32, T);          // warp-per-node grids
    const int W64  = cdiv((M / 2 + 1) * 32, T);

    // ---- layer 1: d = 64 -> 128 ----
    agg_csr<16><<<W64, T>>>((const float4*)x, start, perm, mhi, mlo, M);
    gemm_mma<true><<<dim3(MT, 1), 256, SMEM_GEMM>>>(
        mhi, mlo, xhi, xlo, wp[0], wp[1], wp[2], wp[3],
        bl1, h, hhi, hlo, M, HID, IN_DIM);

    // ---- layer 2: d = 128 -> 128 ----
    agg_csr<32><<<W128, T>>>((const float4*)h, start, perm, mhi, mlo, M);
    gemm_mma<true><<<dim3(MT, 1), 256, SMEM_GEMM>>>(
        mhi, mlo, hhi, hlo, wp[4], wp[5], wp[6], wp[7],
        bl2, h, hhi, hlo, M, HID, HID);

    // ---- layer 3: d = 128 -> 256 ----
    agg_csr<32><<<W128, T>>>((const float4*)h, start, perm, mhi, mlo, M);
    gemm_mma<false><<<dim3(MT, 2), 256, SMEM_GEMM>>>(
        mhi, mlo, hhi, hlo, wp[8], wp[9], wp[10], wp[11],
        bl3, h3, nullptr, nullptr, M, 2 * HID, HID);

    // ---- FC head ----
    fc_kernel<<<cdiv(M * 32, T), T>>>(h3, Wfc, bfc, out, M);
}

// round 8
// speedup vs baseline: 1.0058x; 1.0058x over previous
#include <cuda_runtime.h>
#include <cuda_bf16.h>
#include <cstdint>

// ---------------- problem constants ----------------
#define N_NODES 100000
#define N_EDGES 1600000
#define IN_DIM 64
#define HID 128
#define OUT_DIM 9

// ---------------- static scratch (no allocation allowed) ----------------
__device__ int g_cnt[N_NODES];
__device__ int g_start[N_NODES + 1];
__device__ int g_cursor[N_NODES];
__device__ int g_perm[N_EDGES];
__device__ int g_bsum[512];

__device__ __nv_bfloat16 g_xhi[(size_t)N_NODES * IN_DIM];
__device__ __nv_bfloat16 g_xlo[(size_t)N_NODES * IN_DIM];
__device__ __nv_bfloat16 g_mhi[(size_t)N_NODES * HID];         // mean hi
__device__ __nv_bfloat16 g_mlo[(size_t)N_NODES * HID];         // mean lo
__device__ float g_h[(size_t)N_NODES * HID];                   // h1 then h2 (fp32, gather source)
__device__ __nv_bfloat16 g_hhi[(size_t)N_NODES * HID];
__device__ __nv_bfloat16 g_hlo[(size_t)N_NODES * HID];
__device__ float g_h3[(size_t)N_NODES * 2 * HID];
// static weight buffers (bf16, transposed [N,K]); order: l1l_hi,l1l_lo,l1r_hi,l1r_lo, l2..., l3...
__device__ __nv_bfloat16 g_w[12][256 * 128];

// ---------------- PTX helpers (all plain sm_80+ — no 'a' features) ----------------
__device__ __forceinline__ uint32_t smem_u32(const void* p) {
    uint32_t a;
    asm("{ .reg .u64 t; cvta.to.shared.u64 t, %1; cvt.u32.u64 %0, t; }" : "=r"(a) : "l"(p));
    return a;
}

__device__ __forceinline__ void cp_async16(uint32_t dst, const void* src, int src_bytes) {
    asm volatile("cp.async.cg.shared.global [%0], [%1], 16, %2;"
                 :: "r"(dst), "l"(src), "r"(src_bytes));
}
#define CP_COMMIT() asm volatile("cp.async.commit_group;" ::: "memory")
#define CP_WAIT_1() asm volatile("cp.async.wait_group 1;" ::: "memory")

__device__ __forceinline__ void ldm_x4(uint32_t& r0, uint32_t& r1, uint32_t& r2, uint32_t& r3,
                                       uint32_t addr) {
    asm volatile("ldmatrix.sync.aligned.m8n8.x4.shared.b16 {%0,%1,%2,%3}, [%4];"
                 : "=r"(r0), "=r"(r1), "=r"(r2), "=r"(r3) : "r"(addr));
}

__device__ __forceinline__ void mma_16816(float* c, const uint32_t* a, const uint32_t* b) {
    asm volatile(
        "mma.sync.aligned.m16n8k16.row.col.f32.bf16.bf16.f32 "
        "{%0,%1,%2,%3}, {%4,%5,%6,%7}, {%8,%9}, {%0,%1,%2,%3};"
        : "+f"(c[0]), "+f"(c[1]), "+f"(c[2]), "+f"(c[3])
        : "r"(a[0]), "r"(a[1]), "r"(a[2]), "r"(a[3]), "r"(b[0]), "r"(b[1]));
}

// ---------------- CSR build kernels ----------------
__global__ void zero_int(int* __restrict__ p, int n) {
    int i = blockIdx.x * blockDim.x + threadIdx.x;
    if (i < n) p[i] = 0;
}

__global__ void hist_kernel(const int* __restrict__ dst, int* __restrict__ cnt, int E) {
    int e = blockIdx.x * blockDim.x + threadIdx.x;
    if (e < E) atomicAdd(&cnt[dst[e]], 1);
}

#define SCAN_B 256
__global__ void block_sum(const int* __restrict__ cnt, int* __restrict__ bsum, int n) {
    __shared__ int sh[SCAN_B];
    int i = blockIdx.x * SCAN_B + threadIdx.x;
    sh[threadIdx.x] = (i < n) ? cnt[i] : 0;
    __syncthreads();
    #pragma unroll
    for (int off = SCAN_B / 2; off > 0; off >>= 1) {
        if (threadIdx.x < off) sh[threadIdx.x] += sh[threadIdx.x + off];
        __syncthreads();
    }
    if (threadIdx.x == 0) bsum[blockIdx.x] = sh[0];
}

// single block of 512 threads: exclusive scan of nb block sums; also writes start[N]=E total
__global__ void scan_bsums(int* __restrict__ bsum, int nb, int* __restrict__ startN) {
    __shared__ int sh[512];
    int t = threadIdx.x;
    int orig = (t < nb) ? bsum[t] : 0;
    sh[t] = orig;
    __syncthreads();
    #pragma unroll
    for (int off = 1; off < 512; off <<= 1) {
        int v = (t >= off) ? sh[t - off] : 0;
        __syncthreads();
        sh[t] += v;
        __syncthreads();
    }
    if (t < nb) bsum[t] = sh[t] - orig;   // exclusive prefix
    if (t == 0) startN[0] = sh[511];      // total = E
}

__global__ void block_scan(const int* __restrict__ cnt, const int* __restrict__ boff,
                           int* __restrict__ start, int* __restrict__ cursor, int n) {
    __shared__ int sh[SCAN_B];
    int i = blockIdx.x * SCAN_B + threadIdx.x;
    int t = threadIdx.x;
    int v = (i < n) ? cnt[i] : 0;
    sh[t] = v;
    __syncthreads();
    #pragma unroll
    for (int off = 1; off < SCAN_B; off <<= 1) {
        int u = (t >= off) ? sh[t - off] : 0;
        __syncthreads();
        sh[t] += u;
        __syncthreads();
    }
    if (i < n) {
        int ex = boff[blockIdx.x] + sh[t] - v;
        start[i] = ex;
        cursor[i] = ex;
    }
}

__global__ void fill_perm(const int* __restrict__ src, const int* __restrict__ dst,
                          int* __restrict__ cursor, int* __restrict__ perm, int E) {
    int e = blockIdx.x * blockDim.x + threadIdx.x;
    if (e < E) {
        int pos = atomicAdd(&cursor[dst[e]], 1);
        perm[pos] = src[e];
    }
}

// ---------------- CSR gather-aggregate + mean + bf16 hi/lo split ----------------
// DV = feature dim / 4 (float4 units per row). DV=32: warp per node. DV=16: 2 nodes per warp.
template <int DV>
__global__ __launch_bounds__(256)
void agg_csr(const float4* __restrict__ x, const int* __restrict__ start,
             const int* __restrict__ perm,
             __nv_bfloat16* __restrict__ hi, __nv_bfloat16* __restrict__ lo, int n) {
    int gw = (blockIdx.x * blockDim.x + threadIdx.x) >> 5;
    int lane = threadIdx.x & 31;
    int node, c;
    if (DV == 32) { node = gw; c = lane; }
    else          { node = gw * 2 + (lane >> 4); c = lane & 15; }
    if (node >= n) return;
    int s = __ldg(&start[node]);
    int e = __ldg(&start[node + 1]);
    float4 acc = make_float4(0.f, 0.f, 0.f, 0.f);
    int j = s;
    for (; j + 4 <= e; j += 4) {
        int p0 = __ldg(&perm[j]);
        int p1 = __ldg(&perm[j + 1]);
        int p2 = __ldg(&perm[j + 2]);
        int p3 = __ldg(&perm[j + 3]);
        float4 v0 = __ldg(&x[(size_t)p0 * DV + c]);
        float4 v1 = __ldg(&x[(size_t)p1 * DV + c]);
        float4 v2 = __ldg(&x[(size_t)p2 * DV + c]);
        float4 v3 = __ldg(&x[(size_t)p3 * DV + c]);
        acc.x += v0.x + v1.x + v2.x + v3.x;
        acc.y += v0.y + v1.y + v2.y + v3.y;
        acc.z += v0.z + v1.z + v2.z + v3.z;
        acc.w += v0.w + v1.w + v2.w + v3.w;
    }
    for (; j < e; j++) {
        int p = __ldg(&perm[j]);
        float4 v = __ldg(&x[(size_t)p * DV + c]);
        acc.x += v.x; acc.y += v.y; acc.z += v.z; acc.w += v.w;
    }
    float r = 1.0f / fmaxf((float)(e - s), 1.0f);
    float m[4] = {acc.x * r, acc.y * r, acc.z * r, acc.w * r};
    __nv_bfloat16 hb[4], lb[4];
    #pragma unroll
    for (int q = 0; q < 4; q++) {
        hb[q] = __float2bfloat16(m[q]);
        lb[q] = __float2bfloat16(m[q] - __bfloat162float(hb[q]));
    }
    size_t off = (size_t)node * (DV * 4) + c * 4;
    *(uint2*)(hi + off) = *(uint2*)hb;
    *(uint2*)(lo + off) = *(uint2*)lb;
}

// ---------------- misc split kernels ----------------
__global__ void split_kernel(const float* __restrict__ x,
                             __nv_bfloat16* __restrict__ hi, __nv_bfloat16* __restrict__ lo, int n) {
    int i = blockIdx.x * blockDim.x + threadIdx.x;
    if (i >= n) return;
    float v = x[i];
    __nv_bfloat16 h = __float2bfloat16(v);
    hi[i] = h;
    lo[i] = __float2bfloat16(v - __bfloat162float(h));
}

__global__ void wsplit_kernel(const float* __restrict__ W,
                              __nv_bfloat16* __restrict__ hi, __nv_bfloat16* __restrict__ lo,
                              int K, int N) {
    int idx = blockIdx.x * blockDim.x + threadIdx.x;
    if (idx >= K * N) return;
    int k = idx / N, n = idx % N;
    float v = W[idx];
    __nv_bfloat16 h = __float2bfloat16(v);
    hi[(size_t)n * K + k] = h;
    lo[(size_t)n * K + k] = __float2bfloat16(v - __bfloat162float(h));
}

// ---------------- mma.sync dual-A split-bf16 GEMM (unchanged from R5, passing) ----------------
template <bool SPLIT_OUT>
__global__ __launch_bounds__(256, 2)
void gemm_mma(const __nv_bfloat16* __restrict__ A1hi, const __nv_bfloat16* __restrict__ A1lo,
              const __nv_bfloat16* __restrict__ A2hi, const __nv_bfloat16* __restrict__ A2lo,
              const __nv_bfloat16* __restrict__ B1hi, const __nv_bfloat16* __restrict__ B1lo,
              const __nv_bfloat16* __restrict__ B2hi, const __nv_bfloat16* __restrict__ B2lo,
              const float* __restrict__ bias, float* __restrict__ C,
              __nv_bfloat16* __restrict__ Chi, __nv_bfloat16* __restrict__ Clo,
              int M, int Ntot, int Kseg) {
    extern __shared__ char smem_raw[];
    char* smem = (char*)(((uintptr_t)smem_raw + 127) & ~(uintptr_t)127);
    const uint32_t sbase = smem_u32(smem);

    const int tid = threadIdx.x;
    const int wid = tid >> 5;
    const int lane = tid & 31;
    const int warp_m = wid & 3;
    const int warp_n = wid >> 2;
    const int bm = blockIdx.x * 128;
    const int bn = blockIdx.y * 128;

    const int STG = 32768;
    const int BOFF = 16384;

    const __nv_bfloat16* As[6] = {A1hi, A1hi, A1lo, A2hi, A2hi, A2lo};
    const __nv_bfloat16* Bs[6] = {B1hi, B1lo, B1hi, B2hi, B2lo, B2hi};
    const int cps = Kseg >> 6;
    const int nch = 6 * cps;

    float acc[2][8][4];
    #pragma unroll
    for (int mi = 0; mi < 2; mi++)
        #pragma unroll
        for (int ni = 0; ni < 8; ni++)
            #pragma unroll
            for (int q = 0; q < 4; q++) acc[mi][ni][q] = 0.0f;

    auto load_stage = [&](int stage, int c) {
        const int seg = c / cps;
        const int sub = c - seg * cps;
        const __nv_bfloat16* Ab = As[seg];
        const __nv_bfloat16* Bb = Bs[seg];
        const int kofs = sub << 6;
        #pragma unroll
        for (int p = 0; p < 4; p++) {
            int ci = tid + p * 256;
            int row = ci >> 3;
            int ch = ci & 7;
            uint32_t dstp = sbase + stage * STG + row * 128 + ((ch ^ (row & 7)) << 4);
            int grow = bm + row;
            int ok = (grow < M) ? 16 : 0;
            int gr = (grow < M) ? grow : (M - 1);
            cp_async16(dstp, Ab + (size_t)gr * Kseg + kofs + ch * 8, ok);
        }
        #pragma unroll
        for (int p = 0; p < 4; p++) {
            int ci = tid + p * 256;
            int row = ci >> 3;
            int ch = ci & 7;
            uint32_t dstp = sbase + stage * STG + BOFF + row * 128 + ((ch ^ (row & 7)) << 4);
            cp_async16(dstp, Bb + (size_t)(bn + row) * Kseg + kofs + ch * 8, 16);
        }
    };

    const int arow = warp_m * 32 + (lane & 15);
    const int asel = (lane >> 4);
    const int brow = warp_n * 64 + (lane & 7) + ((lane & 16) >> 1);
    const int bsel = (lane >> 3) & 1;

    load_stage(0, 0);
    CP_COMMIT();

    for (int c = 0; c < nch; c++) {
        const int s = c & 1;
        if (c + 1 < nch) load_stage(s ^ 1, c + 1);
        CP_COMMIT();
        CP_WAIT_1();
        __syncthreads();

        const uint32_t Abase = sbase + s * STG;
        const uint32_t Bbase = sbase + s * STG + BOFF;
        #pragma unroll
        for (int kc = 0; kc < 4; kc++) {
            uint32_t a[2][4];
            #pragma unroll
            for (int mi = 0; mi < 2; mi++) {
                int r = arow + mi * 16;
                uint32_t ad = Abase + r * 128 + (((kc * 2 + asel) ^ (r & 7)) << 4);
                ldm_x4(a[mi][0], a[mi][1], a[mi][2], a[mi][3], ad);
            }
            uint32_t b[8][2];
            #pragma unroll
            for (int nj = 0; nj < 4; nj++) {
                int r = brow + nj * 16;
                uint32_t bd = Bbase + r * 128 + (((kc * 2 + bsel) ^ (r & 7)) << 4);
                uint32_t t0, t1, t2, t3;
                ldm_x4(t0, t1, t2, t3, bd);
                b[nj * 2][0] = t0; b[nj * 2][1] = t1;
                b[nj * 2 + 1][0] = t2; b[nj * 2 + 1][1] = t3;
            }
            #pragma unroll
            for (int mi = 0; mi < 2; mi++)
                #pragma unroll
                for (int ni = 0; ni < 8; ni++)
                    mma_16816(acc[mi][ni], a[mi], b[ni]);
        }
        __syncthreads();
    }

    const int col0 = bn + warp_n * 64 + (lane & 3) * 2;
    #pragma unroll
    for (int mi = 0; mi < 2; mi++) {
        int row0 = bm + warp_m * 32 + mi * 16 + (lane >> 2);
        #pragma unroll
        for (int half = 0; half < 2; half++) {
            int row = row0 + half * 8;
            if (row >= M) continue;
            #pragma unroll
            for (int ni = 0; ni < 8; ni++) {
                int col = col0 + ni * 8;
                float v0 = acc[mi][ni][half * 2 + 0] + __ldg(&bias[col]);
                float v1 = acc[mi][ni][half * 2 + 1] + __ldg(&bias[col + 1]);
                v0 = fmaxf(v0, 0.0f);
                v1 = fmaxf(v1, 0.0f);
                *(float2*)(C + (size_t)row * Ntot + col) = make_float2(v0, v1);
                if (SPLIT_OUT) {
                    __nv_bfloat16 h0 = __float2bfloat16(v0);
                    __nv_bfloat16 h1 = __float2bfloat16(v1);
                    __nv_bfloat16 l0 = __float2bfloat16(v0 - __bfloat162float(h0));
                    __nv_bfloat16 l1 = __float2bfloat16(v1 - __bfloat162float(h1));
                    *(__nv_bfloat162*)(Chi + (size_t)row * Ntot + col) = __nv_bfloat162(h0, h1);
                    *(__nv_bfloat162*)(Clo + (size_t)row * Ntot + col) = __nv_bfloat162(l0, l1);
                }
            }
        }
    }
}

// ---------------- FC head: out[i,0..8] = h3[i,:]@Wfc + bfc (warp per node) ----
__global__ void fc_kernel(const float* __restrict__ h3, const float* __restrict__ W,
                          const float* __restrict__ b, float* __restrict__ out, int M) {
    int gwarp = (blockIdx.x * blockDim.x + threadIdx.x) >> 5;
    int lane = threadIdx.x & 31;
    if (gwarp >= M) return;
    const float* row = h3 + (size_t)gwarp * (2 * HID);
    float acc[OUT_DIM];
    #pragma unroll
    for (int j = 0; j < OUT_DIM; j++) acc[j] = 0.0f;
    for (int k = lane; k < 2 * HID; k += 32) {
        float a = row[k];
        #pragma unroll
        for (int j = 0; j < OUT_DIM; j++)
            acc[j] = fmaf(a, W[k * OUT_DIM + j], acc[j]);
    }
    #pragma unroll
    for (int j = 0; j < OUT_DIM; j++) {
        #pragma unroll
        for (int off = 16; off > 0; off >>= 1)
            acc[j] += __shfl_down_sync(0xffffffffu, acc[j], off);
    }
    if (lane == 0) {
        #pragma unroll
        for (int j = 0; j < OUT_DIM; j++)
            out[(size_t)gwarp * OUT_DIM + j] = acc[j] + b[j];
    }
}

// ---------------- host launch ----------------
static inline int cdiv(int a, int b) { return (a + b - 1) / b; }

extern "C" void kernel_launch(void* const* d_in, const int* in_sizes, int n_in,
                              void* d_out, int out_size) {
    const float* x   = (const float*)d_in[0];
    const int* eidx  = (const int*)d_in[1];
    const float* Wl1 = (const float*)d_in[2];
    const float* bl1 = (const float*)d_in[3];
    const float* Wr1 = (const float*)d_in[4];
    const float* Wl2 = (const float*)d_in[5];
    const float* bl2 = (const float*)d_in[6];
    const float* Wr2 = (const float*)d_in[7];
    const float* Wl3 = (const float*)d_in[8];
    const float* bl3 = (const float*)d_in[9];
    const float* Wr3 = (const float*)d_in[10];
    const float* Wfc = (const float*)d_in[11];
    const float* bfc = (const float*)d_in[12];
    float* out = (float*)d_out;

    const int M = in_sizes[0] / IN_DIM;       // 100000
    const int E = in_sizes[1] / 2;            // 1600000
    const int* src = eidx;
    const int* dst = eidx + E;

    float *h, *h3;
    int *cnt, *start, *cursor, *perm, *bsum;
    __nv_bfloat16 *xhi, *xlo, *mhi, *mlo, *hhi, *hlo, *w;
    cudaGetSymbolAddress((void**)&cnt, g_cnt);
    cudaGetSymbolAddress((void**)&start, g_start);
    cudaGetSymbolAddress((void**)&cursor, g_cursor);
    cudaGetSymbolAddress((void**)&perm, g_perm);
    cudaGetSymbolAddress((void**)&bsum, g_bsum);
    cudaGetSymbolAddress((void**)&h, g_h);
    cudaGetSymbolAddress((void**)&h3, g_h3);
    cudaGetSymbolAddress((void**)&xhi, g_xhi);
    cudaGetSymbolAddress((void**)&xlo, g_xlo);
    cudaGetSymbolAddress((void**)&mhi, g_mhi);
    cudaGetSymbolAddress((void**)&mlo, g_mlo);
    cudaGetSymbolAddress((void**)&hhi, g_hhi);
    cudaGetSymbolAddress((void**)&hlo, g_hlo);
    cudaGetSymbolAddress((void**)&w, g_w);
    const size_t WSTRIDE = 256 * 128;
    __nv_bfloat16* wp[12];
    for (int i = 0; i < 12; i++) wp[i] = w + i * WSTRIDE;

    const int T = 256;
    const int SMEM_GEMM = 2 * 32768 + 128;

    cudaFuncSetAttribute(gemm_mma<true>, cudaFuncAttributeMaxDynamicSharedMemorySize, SMEM_GEMM);
    cudaFuncSetAttribute(gemm_mma<false>, cudaFuncAttributeMaxDynamicSharedMemorySize, SMEM_GEMM);

    // ---- CSR build (once per launch; reused by all 3 layers) ----
    const int NB = cdiv(M, SCAN_B);           // 391
    zero_int<<<cdiv(M, T), T>>>(cnt, M);
    hist_kernel<<<cdiv(E, T), T>>>(dst, cnt, E);
    block_sum<<<NB, SCAN_B>>>(cnt, bsum, M);
    scan_bsums<<<1, 512>>>(bsum, NB, start + M);
    block_scan<<<NB, SCAN_B>>>(cnt, bsum, start, cursor, M);
    fill_perm<<<cdiv(E, T), T>>>(src, dst, cursor, perm, E);

    // ---- one-time splits: x and weights ----
    split_kernel<<<cdiv(M * IN_DIM, T), T>>>(x, xhi, xlo, M * IN_DIM);
    wsplit_kernel<<<cdiv(IN_DIM * HID, T), T>>>(Wl1, wp[0], wp[1], IN_DIM, HID);
    wsplit_kernel<<<cdiv(IN_DIM * HID, T), T>>>(Wr1, wp[2], wp[3], IN_DIM, HID);
    wsplit_kernel<<<cdiv(HID * HID, T), T>>>(Wl2, wp[4], wp[5], HID, HID);
    wsplit_kernel<<<cdiv(HID * HID, T), T>>>(Wr2, wp[6], wp[7], HID, HID);
    wsplit_kernel<<<cdiv(HID * 2 * HID, T), T>>>(Wl3, wp[8], wp[9], HID, 2 * HID);
    wsplit_kernel<<<cdiv(HID * 2 * HID, T), T>>>(Wr3, wp[10], wp[11], HID, 2 * HID);

    const int MT = cdiv(M, 128);   // 782 m-tiles
    const int W128 = cdiv(M * 32, T);          // warp-per-node grids
    const int W64  = cdiv((M / 2 + 1) * 32, T);

    // ---- layer 1: d = 64 -> 128 ----
    agg_csr<16><<<W64, T>>>((const float4*)x, start, perm, mhi, mlo, M);
    gemm_mma<true><<<dim3(MT, 1), 256, SMEM_GEMM>>>(
        mhi, mlo, xhi, xlo, wp[0], wp[1], wp[2], wp[3],
        bl1, h, hhi, hlo, M, HID, IN_DIM);

    // ---- layer 2: d = 128 -> 128 ----
    agg_csr<32><<<W128, T>>>((const float4*)h, start, perm, mhi, mlo, M);
    gemm_mma<true><<<dim3(MT, 1), 256, SMEM_GEMM>>>(
        mhi, mlo, hhi, hlo, wp[4], wp[5], wp[6], wp[7],
        bl2, h, hhi, hlo, M, HID, HID);

    // ---- layer 3: d = 128 -> 256 ----
    agg_csr<32><<<W128, T>>>((const float4*)h, start, perm, mhi, mlo, M);
    gemm_mma<false><<<dim3(MT, 2), 256, SMEM_GEMM>>>(
        mhi, mlo, hhi, hlo, wp[8], wp[9], wp[10], wp[11],
        bl3, h3, nullptr, nullptr, M, 2 * HID, HID);

    // ---- FC head ----
    fc_kernel<<<cdiv(M * 32, T), T>>>(h3, Wfc, bfc, out, M);
}